// round 15
// baseline (speedup 1.0000x reference)
#include <cuda_runtime.h>
#include <cuda_bf16.h>
#include <cuda_fp16.h>
#include <math.h>
#include <stdint.h>

#define B_   4
#define T_   2048
#define E_   1024
#define H_   16
#define ROWS_ (B_ * T_)
#define EPS_ 1e-5f

// ---------------- scratch ----------------
__device__ __half g_xh[ROWS_ * E_];
__device__ __half g_oh[ROWS_ * E_];
__device__ __half g_w16[4][E_ * E_];    // Wk, Wq, Wv, Wu (fp16)
__device__ __half g_q2h[ROWS_ * E_];
__device__ __half g_k2h[ROWS_ * E_];
__device__ __half g_v2h[ROWS_ * E_];

// ---------------- PTX helpers (sm_80-era; compute_103 non-'a' PTX) ---------
__device__ __forceinline__ uint32_t smem_u32(const void* p) {
    uint32_t a;
    asm("{ .reg .u64 t; cvta.to.shared.u64 t, %1; cvt.u32.u64 %0, t; }"
        : "=r"(a) : "l"(p));
    return a;
}
__device__ __forceinline__ void cp16(uint32_t dst, const void* src) {
    asm volatile("cp.async.cg.shared.global [%0], [%1], 16;"
                 :: "r"(dst), "l"(src) : "memory");
}
#define CP_COMMIT() asm volatile("cp.async.commit_group;" ::: "memory")
#define CP_WAIT(n)  asm volatile("cp.async.wait_group %0;" :: "n"(n) : "memory")
#define LDSM_X4(r0, r1, r2, r3, addr) \
    asm volatile("ldmatrix.sync.aligned.m8n8.x4.shared.b16 {%0,%1,%2,%3}, [%4];" \
                 : "=r"(r0), "=r"(r1), "=r"(r2), "=r"(r3) : "r"(addr))
#define LDSM_X4_T(r0, r1, r2, r3, addr) \
    asm volatile("ldmatrix.sync.aligned.m8n8.x4.trans.shared.b16 {%0,%1,%2,%3}, [%4];" \
                 : "=r"(r0), "=r"(r1), "=r"(r2), "=r"(r3) : "r"(addr))

__device__ __forceinline__ void mma_f16(float* d, const uint32_t* a,
                                        uint32_t b0, uint32_t b1) {
    asm volatile(
        "mma.sync.aligned.m16n8k16.row.col.f32.f16.f16.f32 "
        "{%0,%1,%2,%3}, {%4,%5,%6,%7}, {%8,%9}, {%0,%1,%2,%3};"
        : "+f"(d[0]), "+f"(d[1]), "+f"(d[2]), "+f"(d[3])
        : "r"(a[0]), "r"(a[1]), "r"(a[2]), "r"(a[3]), "r"(b0), "r"(b1));
}
__device__ __forceinline__ uint32_t packh2(float a, float b) {
    __half2 t = __floats2half2_rn(a, b);
    return *(uint32_t*)&t;
}

// ---------------- fp32 -> fp16 convert (x + 4 weights in one launch) -------
__global__ __launch_bounds__(256) void conv_all_f16(const float* __restrict__ x,
                                                    const float* __restrict__ w0,
                                                    const float* __restrict__ w1,
                                                    const float* __restrict__ w2,
                                                    const float* __restrict__ w3,
                                                    __half* __restrict__ xo,
                                                    __half* __restrict__ wo) {
    const int nX4 = ROWS_ * E_ / 4;
    const int nW4 = E_ * E_ / 4;
    int i = blockIdx.x * blockDim.x + threadIdx.x;
    const float* src;
    __half* dst;
    int j;
    if (i < nX4) {
        src = x; dst = xo; j = i;
    } else {
        const int k = i - nX4;
        const int m = k / nW4;
        j = k - m * nW4;
        src = (m == 0) ? w0 : (m == 1) ? w1 : (m == 2) ? w2 : w3;
        dst = wo + (size_t)m * nW4 * 4;
    }
    float4 v = ((const float4*)src)[j];
    __half h[4] = {__float2half_rn(v.x), __float2half_rn(v.y),
                   __float2half_rn(v.z), __float2half_rn(v.w)};
    ((uint2*)dst)[j] = *(uint2*)h;
}

// ============================================================================
// fp16 GEMM, single-term A. LNE=1: QKV fused epilogue — z0 = K (per-head LN),
// z1 = Q (per-head LN, scale 1/8), z2 = V (plain fp16). LNE=0: fp32 out.
// CTA 128x128, K-chunk 64, 3-stage cp.async, 8 warps. 2 CTAs/SM enforced.
// ============================================================================
#define GN 1024
#define GK 1024
#define KCH 64
#define NCHUNK (GK / KCH)
#define TILE_BYTES 16384
#define SMEM_G (3 * 2 * TILE_BYTES)   // 98304

template <int LNE>
__global__ __launch_bounds__(256, 2) void gemm_f16(
    const __half* __restrict__ Ah,
    const __half* B0, const __half* B1, const __half* B2,
    __half* outK, __half* outQ, __half* outV,
    float* outC,
    const float* lwk, const float* lbk,
    const float* lwq, const float* lbq) {
    extern __shared__ __align__(1024) char smem[];
    const uint32_t smem_base = smem_u32(smem);

    const __half* Bm = (blockIdx.z == 0) ? B0 : (blockIdx.z == 1) ? B1 : B2;

    const int tid = threadIdx.x;
    const int lane = tid & 31;
    const int wid = tid >> 5;
    const int m0 = blockIdx.y * 128;
    const int n0 = blockIdx.x * 128;
    const int wm = (wid >> 2) * 64;
    const int wn = (wid & 3) * 32;

    const int row2 = tid >> 1;
    const int half = tid & 1;
    const uint32_t lmask = (row2 & 7) << 4;
    const __half* gAh = Ah + (size_t)(m0 + row2) * GK;
    const __half* gB  = Bm + (size_t)(n0 + row2) * GK;

    const int a_lrow = (lane & 7) + ((lane >> 3) & 1) * 8;
    const uint32_t a_lkx = ((lane >> 4) & 1) * 16;
    uint32_t arbase[4], amask[4];
#pragma unroll
    for (int mf = 0; mf < 4; mf++) {
        const int r = wm + mf * 16 + a_lrow;
        arbase[mf] = (uint32_t)r * 128;
        amask[mf] = (r & 7) << 4;
    }
    const int b_lrow = (lane & 7) + ((lane >> 4) & 1) * 8;
    const uint32_t b_lkx = ((lane >> 3) & 1) * 16;
    uint32_t brbase[2], bmask[2];
#pragma unroll
    for (int np = 0; np < 2; np++) {
        const int r = wn + np * 16 + b_lrow;
        brbase[np] = (uint32_t)r * 128;
        bmask[np] = (r & 7) << 4;
    }

    float acc[4][4][4];
#pragma unroll
    for (int i = 0; i < 4; i++)
#pragma unroll
        for (int j = 0; j < 4; j++)
#pragma unroll
            for (int r = 0; r < 4; r++) acc[i][j][r] = 0.f;

    auto issue_load = [&](int c, int s) {
        const uint32_t st = smem_base + s * 2 * TILE_BYTES;
        const int ke = c * KCH;
#pragma unroll
        for (int v = 0; v < 4; v++) {
            const uint32_t koff = half * 64 + v * 16;
            const uint32_t d = row2 * 128 + (koff ^ lmask);
            const int kel = ke + (int)(koff >> 1);
            cp16(st + d, gAh + kel);
            cp16(st + TILE_BYTES + d, gB + kel);
        }
    };

    issue_load(0, 0); CP_COMMIT();
    issue_load(1, 1); CP_COMMIT();

    for (int c = 0; c < NCHUNK; c++) {
        CP_WAIT(1);
        __syncthreads();
        if (c + 2 < NCHUNK) issue_load(c + 2, (c + 2) % 3);
        CP_COMMIT();

        const uint32_t st = smem_base + (c % 3) * 2 * TILE_BYTES;
        const uint32_t stB = st + TILE_BYTES;

#pragma unroll
        for (int ks = 0; ks < 4; ks++) {
            const uint32_t koffA = ks * 32 + a_lkx;
            const uint32_t koffB = ks * 32 + b_lkx;

            uint32_t ah[4][4];
#pragma unroll
            for (int mf = 0; mf < 4; mf++) {
                const uint32_t off = arbase[mf] + (koffA ^ amask[mf]);
                LDSM_X4(ah[mf][0], ah[mf][1], ah[mf][2], ah[mf][3], st + off);
            }
            uint32_t bh[8];
#pragma unroll
            for (int np = 0; np < 2; np++) {
                const uint32_t off = brbase[np] + (koffB ^ bmask[np]);
                LDSM_X4(bh[np * 4 + 0], bh[np * 4 + 1], bh[np * 4 + 2], bh[np * 4 + 3],
                        stB + off);
            }
#pragma unroll
            for (int mf = 0; mf < 4; mf++) {
#pragma unroll
                for (int nf = 0; nf < 4; nf++) {
                    const int ix = (nf >> 1) * 4 + (nf & 1) * 2;
                    mma_f16(acc[mf][nf], ah[mf], bh[ix], bh[ix + 1]);
                }
            }
        }
    }

    const int groupID = lane >> 2;
    const int tig = lane & 3;

    if (LNE == 0) {
        // fp32 epilogue (out-projection)
#pragma unroll
        for (int mf = 0; mf < 4; mf++) {
            const size_t r = (size_t)(m0 + wm + mf * 16 + groupID);
#pragma unroll
            for (int nf = 0; nf < 4; nf++) {
                const int cidx = n0 + wn + nf * 8 + tig * 2;
                *(float2*)(outC + r * GN + cidx) =
                    make_float2(acc[mf][nf][0], acc[mf][nf][1]);
                *(float2*)(outC + (r + 8) * GN + cidx) =
                    make_float2(acc[mf][nf][2], acc[mf][nf][3]);
            }
        }
        return;
    }

    if (blockIdx.z == 2) {
        // V: plain fp16 store
#pragma unroll
        for (int mf = 0; mf < 4; mf++) {
            const size_t r = (size_t)(m0 + wm + mf * 16 + groupID);
#pragma unroll
            for (int nf = 0; nf < 4; nf++) {
                const int cidx = n0 + wn + nf * 8 + tig * 2;
                *(uint32_t*)(outV + r * GN + cidx) =
                    packh2(acc[mf][nf][0], acc[mf][nf][1]);
                *(uint32_t*)(outV + (r + 8) * GN + cidx) =
                    packh2(acc[mf][nf][2], acc[mf][nf][3]);
            }
        }
        return;
    }

    // K (z=0) / Q (z=1): fused per-head LayerNorm epilogue.
    {
        const float* lw = (blockIdx.z == 0) ? lwk : lwq;
        const float* lb = (blockIdx.z == 0) ? lbk : lbq;
        __half* Oh = (blockIdx.z == 0) ? outK : outQ;
        const float scale = (blockIdx.z == 0) ? 1.0f : 0.125f;
        float2* part = (float2*)smem;   // [128 rows][4 col-halves]

        __syncthreads();   // mainloop smem no longer needed
#pragma unroll
        for (int mf = 0; mf < 4; mf++) {
            float s0 = 0.f, ss0 = 0.f, s1 = 0.f, ss1 = 0.f;
#pragma unroll
            for (int nf = 0; nf < 4; nf++) {
                s0 += acc[mf][nf][0] + acc[mf][nf][1];
                ss0 += acc[mf][nf][0] * acc[mf][nf][0]
                     + acc[mf][nf][1] * acc[mf][nf][1];
                s1 += acc[mf][nf][2] + acc[mf][nf][3];
                ss1 += acc[mf][nf][2] * acc[mf][nf][2]
                     + acc[mf][nf][3] * acc[mf][nf][3];
            }
            s0 += __shfl_xor_sync(0xffffffffu, s0, 1);
            s0 += __shfl_xor_sync(0xffffffffu, s0, 2);
            ss0 += __shfl_xor_sync(0xffffffffu, ss0, 1);
            ss0 += __shfl_xor_sync(0xffffffffu, ss0, 2);
            s1 += __shfl_xor_sync(0xffffffffu, s1, 1);
            s1 += __shfl_xor_sync(0xffffffffu, s1, 2);
            ss1 += __shfl_xor_sync(0xffffffffu, ss1, 1);
            ss1 += __shfl_xor_sync(0xffffffffu, ss1, 2);
            if (tig == 0) {
                part[(wm + mf * 16 + groupID) * 4 + (wn >> 5)] =
                    make_float2(s0, ss0);
                part[(wm + mf * 16 + groupID + 8) * 4 + (wn >> 5)] =
                    make_float2(s1, ss1);
            }
        }
        __syncthreads();

        const int wpair = (wn >> 6) * 2;   // smem half-index of this head
        float lww[8], lbb[8];
#pragma unroll
        for (int nf = 0; nf < 4; nf++) {
            const int cl = (wn & 63) + nf * 8 + tig * 2;
            lww[nf * 2 + 0] = lw[cl];     lww[nf * 2 + 1] = lw[cl + 1];
            lbb[nf * 2 + 0] = lb[cl];     lbb[nf * 2 + 1] = lb[cl + 1];
        }
#pragma unroll
        for (int mf = 0; mf < 4; mf++) {
            const int r0 = wm + mf * 16 + groupID;
            float2 pa = part[r0 * 4 + wpair];
            float2 pb = part[r0 * 4 + wpair + 1];
            const float mean0 = (pa.x + pb.x) * (1.f / 64.f);
            const float var0 = (pa.y + pb.y) * (1.f / 64.f) - mean0 * mean0;
            const float rs0 = rsqrtf(var0 + EPS_);
            float2 pc = part[(r0 + 8) * 4 + wpair];
            float2 pd = part[(r0 + 8) * 4 + wpair + 1];
            const float mean1 = (pc.x + pd.x) * (1.f / 64.f);
            const float var1 = (pc.y + pd.y) * (1.f / 64.f) - mean1 * mean1;
            const float rs1 = rsqrtf(var1 + EPS_);
#pragma unroll
            for (int nf = 0; nf < 4; nf++) {
                const int cidx = n0 + wn + nf * 8 + tig * 2;
                float a0 = ((acc[mf][nf][0] - mean0) * rs0 * lww[nf * 2 + 0]
                            + lbb[nf * 2 + 0]) * scale;
                float a1 = ((acc[mf][nf][1] - mean0) * rs0 * lww[nf * 2 + 1]
                            + lbb[nf * 2 + 1]) * scale;
                float a2 = ((acc[mf][nf][2] - mean1) * rs1 * lww[nf * 2 + 0]
                            + lbb[nf * 2 + 0]) * scale;
                float a3 = ((acc[mf][nf][3] - mean1) * rs1 * lww[nf * 2 + 1]
                            + lbb[nf * 2 + 1]) * scale;
                *(uint32_t*)(Oh + (size_t)(m0 + r0) * GN + cidx) = packh2(a0, a1);
                *(uint32_t*)(Oh + (size_t)(m0 + r0 + 8) * GN + cidx) = packh2(a2, a3);
            }
        }
    }
}

// ============================================================================
// Tensor-core causal flash attention, fp16, fixed-shift softmax.
// (unchanged from R14 — validated)
// ============================================================================
#define ATT_SMEM (8192 + 3 * 16384)
#define SM_SHIFT 4.0f

__global__ __launch_bounds__(128, 4) void attn_tc(
    const __half* __restrict__ q2h, const __half* __restrict__ k2h,
    const __half* __restrict__ v2h, __half* __restrict__ ohp) {
    extern __shared__ __align__(1024) char smem[];
    const uint32_t sb = smem_u32(smem);

    const int tid = threadIdx.x;
    const int lane = tid & 31;
    const int wid = tid >> 5;
    const int bh = blockIdx.y;
    const int b = bh >> 4, h = bh & 15;
    const int i0 = (int)(gridDim.x - 1 - blockIdx.x) * 64;
    const int nt = i0 >> 6;
    const size_t hoff = (size_t)b * T_ * E_ + (size_t)h * 64;

    const int row = tid >> 1;
    const int half = tid & 1;
    const uint32_t smask = (uint32_t)((row & 7) << 4);

    const __half* gq = q2h + hoff + (size_t)(i0 + row) * E_ + half * 32;
    const __half* gk = k2h + hoff;
    const __half* gv = v2h + hoff;

    auto issue_tile = [&](int t, int s) {
        const uint32_t st = sb + 8192 + (uint32_t)s * 16384;
        const __half* rk = gk + (size_t)(t * 64 + row) * E_ + half * 32;
        const __half* rv = gv + (size_t)(t * 64 + row) * E_ + half * 32;
#pragma unroll
        for (int v = 0; v < 4; v++) {
            const uint32_t colb = half * 64 + v * 16;
            const uint32_t d = row * 128 + (colb ^ smask);
            cp16(st + d,        rk + v * 8);
            cp16(st + 8192 + d, rv + v * 8);
        }
    };

    {
#pragma unroll
        for (int v = 0; v < 4; v++) {
            const uint32_t colb = half * 64 + v * 16;
            const uint32_t d = row * 128 + (colb ^ smask);
            cp16(sb + d, gq + v * 8);
        }
        issue_tile(0, 0); CP_COMMIT();
        if (nt >= 1) issue_tile(1, 1);
        CP_COMMIT();
    }

    const int gid = lane >> 2, tig = lane & 3;
    const int wm = wid * 16;
    const int a_lrow = wm + (lane & 7) + ((lane >> 3) & 1) * 8;
    const uint32_t a_off = (uint32_t)a_lrow * 128;
    const uint32_t a_lkx = ((lane >> 4) & 1) * 16;
    const uint32_t a_mask = (uint32_t)((a_lrow & 7) << 4);
    const int b_lrow = (lane & 7) + ((lane >> 4) & 1) * 8;
    const uint32_t b_lkx = ((lane >> 3) & 1) * 16;
    const int vt_r = ((lane >> 3) & 1) * 8 + (lane & 7);
    const uint32_t vt_cx = ((lane >> 4) & 1) * 16;
    const int il0 = wm + gid, il1 = wm + gid + 8;

    float oacc[8][4];
#pragma unroll
    for (int i = 0; i < 8; i++)
#pragma unroll
        for (int r = 0; r < 4; r++) oacc[i][r] = 0.f;
    float l0 = 0.f, l1 = 0.f;
    uint32_t aP[16];
    uint32_t aQ[4][4];

    auto do_S_softmax = [&](uint32_t stK, bool isLast) {
#pragma unroll
        for (int jg = 0; jg < 4; jg++) {
            float s8[8];
#pragma unroll
            for (int r = 0; r < 8; r++) s8[r] = 0.f;
            const int r2 = jg * 16 + b_lrow;
            const uint32_t rbase = (uint32_t)r2 * 128;
            const uint32_t rmask = (uint32_t)((r2 & 7) << 4);
#pragma unroll
            for (int kc = 0; kc < 4; kc++) {
                uint32_t kb[4];
                LDSM_X4(kb[0], kb[1], kb[2], kb[3],
                        stK + rbase + (((uint32_t)kc * 32 + b_lkx) ^ rmask));
                mma_f16(&s8[0], aQ[kc], kb[0], kb[1]);
                mma_f16(&s8[4], aQ[kc], kb[2], kb[3]);
            }
            if (isLast) {
                const int jc0 = jg * 16 + tig * 2;
                const int jc1 = jc0 + 8;
                if (jc0 > il0)     s8[0] = -1e30f;
                if (jc0 + 1 > il0) s8[1] = -1e30f;
                if (jc0 > il1)     s8[2] = -1e30f;
                if (jc0 + 1 > il1) s8[3] = -1e30f;
                if (jc1 > il0)     s8[4] = -1e30f;
                if (jc1 + 1 > il0) s8[5] = -1e30f;
                if (jc1 > il1)     s8[6] = -1e30f;
                if (jc1 + 1 > il1) s8[7] = -1e30f;
            }
#pragma unroll
            for (int r = 0; r < 8; r++) s8[r] = __expf(s8[r] - SM_SHIFT);
            l0 += s8[0] + s8[1] + s8[4] + s8[5];
            l1 += s8[2] + s8[3] + s8[6] + s8[7];
            aP[jg * 4 + 0] = packh2(s8[0], s8[1]);
            aP[jg * 4 + 1] = packh2(s8[2], s8[3]);
            aP[jg * 4 + 2] = packh2(s8[4], s8[5]);
            aP[jg * 4 + 3] = packh2(s8[6], s8[7]);
        }
    };

    auto do_PV = [&](uint32_t stV) {
#pragma unroll
        for (int kc = 0; kc < 4; kc++) {
            const int jr = kc * 16 + vt_r;
            const uint32_t vrow = (uint32_t)jr * 128;
            const uint32_t vmask = (uint32_t)((jr & 7) << 4);
#pragma unroll
            for (int dp = 0; dp < 4; dp++) {
                const uint32_t off = vrow + (((uint32_t)dp * 32 + vt_cx) ^ vmask);
                uint32_t vv[4];
                LDSM_X4_T(vv[0], vv[1], vv[2], vv[3], stV + off);
                mma_f16(oacc[dp * 2], &aP[kc * 4], vv[0], vv[1]);
                mma_f16(oacc[dp * 2 + 1], &aP[kc * 4], vv[2], vv[3]);
            }
        }
    };

    for (int jt = 0; jt <= nt; jt++) {
        CP_WAIT(1);
        __syncthreads();
        if (jt == 0) {
#pragma unroll
            for (int kc = 0; kc < 4; kc++)
                LDSM_X4(aQ[kc][0], aQ[kc][1], aQ[kc][2], aQ[kc][3],
                        sb + a_off + (((uint32_t)kc * 32 + a_lkx) ^ a_mask));
        }
        if (jt + 2 <= nt) issue_tile(jt + 2, (jt + 2) % 3);
        CP_COMMIT();

        const uint32_t st = sb + 8192 + (uint32_t)(jt % 3) * 16384;
        do_S_softmax(st, jt == nt);
        do_PV(st + 8192);
    }

    l0 += __shfl_xor_sync(0xffffffffu, l0, 1);
    l0 += __shfl_xor_sync(0xffffffffu, l0, 2);
    l1 += __shfl_xor_sync(0xffffffffu, l1, 1);
    l1 += __shfl_xor_sync(0xffffffffu, l1, 2);

    const float inv0 = 1.f / l0, inv1 = 1.f / l1;
    const int r0g = b * T_ + i0 + wm + gid;
#pragma unroll
    for (int df = 0; df < 8; df++) {
        const int d = df * 8 + tig * 2;
        const size_t i1 = (size_t)r0g * E_ + h * 64 + d;
        const size_t i2 = (size_t)(r0g + 8) * E_ + h * 64 + d;
        *(uint32_t*)(ohp + i1) = packh2(oacc[df][0] * inv0, oacc[df][1] * inv0);
        *(uint32_t*)(ohp + i2) = packh2(oacc[df][2] * inv1, oacc[df][3] * inv1);
    }
}

// ---------------------------------------------------------------------------
// Launch
// ---------------------------------------------------------------------------
extern "C" void kernel_launch(void* const* d_in, const int* in_sizes, int n_in,
                              void* d_out, int out_size) {
    const float* x     = (const float*)d_in[0];
    const float* Wk    = (const float*)d_in[1];
    const float* Wq    = (const float*)d_in[2];
    const float* Wv    = (const float*)d_in[3];
    const float* Wu    = (const float*)d_in[4];
    const float* kln_w = (const float*)d_in[5];
    const float* kln_b = (const float*)d_in[6];
    const float* qln_w = (const float*)d_in[7];
    const float* qln_b = (const float*)d_in[8];
    float* out = (float*)d_out;

    __half *xh, *oh, *w16, *q2h, *k2h, *v2h;
    cudaGetSymbolAddress((void**)&xh, g_xh);
    cudaGetSymbolAddress((void**)&oh, g_oh);
    cudaGetSymbolAddress((void**)&w16, g_w16);
    cudaGetSymbolAddress((void**)&q2h, g_q2h);
    cudaGetSymbolAddress((void**)&k2h, g_k2h);
    cudaGetSymbolAddress((void**)&v2h, g_v2h);

    __half* wk16 = w16 + 0 * (size_t)E_ * E_;
    __half* wq16 = w16 + 1 * (size_t)E_ * E_;
    __half* wv16 = w16 + 2 * (size_t)E_ * E_;
    __half* wu16 = w16 + 3 * (size_t)E_ * E_;

    cudaFuncSetAttribute(gemm_f16<1>,
                         cudaFuncAttributeMaxDynamicSharedMemorySize, SMEM_G);
    cudaFuncSetAttribute(gemm_f16<0>,
                         cudaFuncAttributeMaxDynamicSharedMemorySize, SMEM_G);
    cudaFuncSetAttribute(attn_tc,
                         cudaFuncAttributeMaxDynamicSharedMemorySize, ATT_SMEM);

    const int nconv = ROWS_ * E_ / 4 + 4 * (E_ * E_ / 4);
    conv_all_f16<<<(nconv + 255) / 256, 256>>>(x, Wk, Wq, Wv, Wu, xh, w16);

    // QKV with fused K/Q LayerNorm epilogue (z0=K, z1=Q, z2=V)
    dim3 gQKV(E_ / 128, ROWS_ / 128, 3);
    gemm_f16<1><<<gQKV, 256, SMEM_G>>>(
        xh, wk16, wq16, wv16, k2h, q2h, v2h, nullptr,
        kln_w, kln_b, qln_w, qln_b);

    dim3 gAttn(T_ / 64, B_ * H_);
    attn_tc<<<gAttn, 128, ATT_SMEM>>>(q2h, k2h, v2h, oh);

    // out-projection: fp32 output
    dim3 gOut(E_ / 128, ROWS_ / 128, 1);
    gemm_f16<0><<<gOut, 256, SMEM_G>>>(
        oh, wu16, wu16, wu16, nullptr, nullptr, nullptr, out,
        nullptr, nullptr, nullptr, nullptr);
}

// round 16
// speedup vs baseline: 1.0472x; 1.0472x over previous
#include <cuda_runtime.h>
#include <cuda_bf16.h>
#include <cuda_fp16.h>
#include <math.h>
#include <stdint.h>

#define B_   4
#define T_   2048
#define E_   1024
#define H_   16
#define ROWS_ (B_ * T_)
#define EPS_ 1e-5f

// ---------------- scratch ----------------
__device__ __half g_xh[ROWS_ * E_];
__device__ __half g_oh[ROWS_ * E_];
__device__ __half g_w16[4][E_ * E_];    // Wk, Wq, Wv, Wu (fp16)
__device__ __half g_q2h[ROWS_ * E_];
__device__ __half g_k2h[ROWS_ * E_];
__device__ __half g_v2h[ROWS_ * E_];

// ---------------- PTX helpers (sm_80-era; compute_103 non-'a' PTX) ---------
__device__ __forceinline__ uint32_t smem_u32(const void* p) {
    uint32_t a;
    asm("{ .reg .u64 t; cvta.to.shared.u64 t, %1; cvt.u32.u64 %0, t; }"
        : "=r"(a) : "l"(p));
    return a;
}
__device__ __forceinline__ void cp16(uint32_t dst, const void* src) {
    asm volatile("cp.async.cg.shared.global [%0], [%1], 16;"
                 :: "r"(dst), "l"(src) : "memory");
}
#define CP_COMMIT() asm volatile("cp.async.commit_group;" ::: "memory")
#define CP_WAIT(n)  asm volatile("cp.async.wait_group %0;" :: "n"(n) : "memory")
#define LDSM_X4(r0, r1, r2, r3, addr) \
    asm volatile("ldmatrix.sync.aligned.m8n8.x4.shared.b16 {%0,%1,%2,%3}, [%4];" \
                 : "=r"(r0), "=r"(r1), "=r"(r2), "=r"(r3) : "r"(addr))
#define LDSM_X4_T(r0, r1, r2, r3, addr) \
    asm volatile("ldmatrix.sync.aligned.m8n8.x4.trans.shared.b16 {%0,%1,%2,%3}, [%4];" \
                 : "=r"(r0), "=r"(r1), "=r"(r2), "=r"(r3) : "r"(addr))

__device__ __forceinline__ void mma_f16(float* d, const uint32_t* a,
                                        uint32_t b0, uint32_t b1) {
    asm volatile(
        "mma.sync.aligned.m16n8k16.row.col.f32.f16.f16.f32 "
        "{%0,%1,%2,%3}, {%4,%5,%6,%7}, {%8,%9}, {%0,%1,%2,%3};"
        : "+f"(d[0]), "+f"(d[1]), "+f"(d[2]), "+f"(d[3])
        : "r"(a[0]), "r"(a[1]), "r"(a[2]), "r"(a[3]), "r"(b0), "r"(b1));
}
__device__ __forceinline__ uint32_t packh2(float a, float b) {
    __half2 t = __floats2half2_rn(a, b);
    return *(uint32_t*)&t;
}

// ---------------- fp32 -> fp16 convert (x + 4 weights in one launch) -------
__global__ __launch_bounds__(256) void conv_all_f16(const float* __restrict__ x,
                                                    const float* __restrict__ w0,
                                                    const float* __restrict__ w1,
                                                    const float* __restrict__ w2,
                                                    const float* __restrict__ w3,
                                                    __half* __restrict__ xo,
                                                    __half* __restrict__ wo) {
    const int nX4 = ROWS_ * E_ / 4;
    const int nW4 = E_ * E_ / 4;
    int i = blockIdx.x * blockDim.x + threadIdx.x;
    const float* src;
    __half* dst;
    int j;
    if (i < nX4) {
        src = x; dst = xo; j = i;
    } else {
        const int k = i - nX4;
        const int m = k / nW4;
        j = k - m * nW4;
        src = (m == 0) ? w0 : (m == 1) ? w1 : (m == 2) ? w2 : w3;
        dst = wo + (size_t)m * nW4 * 4;
    }
    float4 v = ((const float4*)src)[j];
    __half h[4] = {__float2half_rn(v.x), __float2half_rn(v.y),
                   __float2half_rn(v.z), __float2half_rn(v.w)};
    ((uint2*)dst)[j] = *(uint2*)h;
}

// ============================================================================
// fp16 GEMM, single-term A. LNE=1: QKV fused epilogue — z0 = K (per-head LN),
// z1 = Q (per-head LN, scale 1/8), z2 = V (plain fp16). LNE=0: fp32 out.
// CTA 128x128, 512 threads (16 warps, warp tile 32x32), K-chunk 64,
// 3-stage cp.async, 2 CTAs/SM -> 50% occupancy target.
// ============================================================================
#define GN 1024
#define GK 1024
#define KCH 64
#define NCHUNK (GK / KCH)
#define TILE_BYTES 16384
#define SMEM_G (3 * 2 * TILE_BYTES)   // 98304

template <int LNE>
__global__ __launch_bounds__(512, 2) void gemm_f16(
    const __half* __restrict__ Ah,
    const __half* B0, const __half* B1, const __half* B2,
    __half* outK, __half* outQ, __half* outV,
    float* outC,
    const float* lwk, const float* lbk,
    const float* lwq, const float* lbq) {
    extern __shared__ __align__(1024) char smem[];
    const uint32_t smem_base = smem_u32(smem);

    const __half* Bm = (blockIdx.z == 0) ? B0 : (blockIdx.z == 1) ? B1 : B2;

    const int tid = threadIdx.x;
    const int lane = tid & 31;
    const int wid = tid >> 5;           // 0..15
    const int m0 = blockIdx.y * 128;
    const int n0 = blockIdx.x * 128;
    const int wm = (wid >> 2) * 32;     // 0,32,64,96
    const int wn = (wid & 3) * 32;      // 0,32,64,96

    // loader: 4 threads/row, 2x16B per tile each
    const int lrow = tid >> 2;          // 0..127
    const int lq = tid & 3;
    const uint32_t lmask = (uint32_t)((lrow & 7) << 4);
    const __half* gAh = Ah + (size_t)(m0 + lrow) * GK;
    const __half* gB  = Bm + (size_t)(n0 + lrow) * GK;

    const int a_lrow = (lane & 7) + ((lane >> 3) & 1) * 8;
    const uint32_t a_lkx = ((lane >> 4) & 1) * 16;
    uint32_t arbase[2], amask[2];
#pragma unroll
    for (int mf = 0; mf < 2; mf++) {
        const int r = wm + mf * 16 + a_lrow;
        arbase[mf] = (uint32_t)r * 128;
        amask[mf] = (uint32_t)((r & 7) << 4);
    }
    const int b_lrow = (lane & 7) + ((lane >> 4) & 1) * 8;
    const uint32_t b_lkx = ((lane >> 3) & 1) * 16;
    uint32_t brbase[2], bmask[2];
#pragma unroll
    for (int np = 0; np < 2; np++) {
        const int r = wn + np * 16 + b_lrow;
        brbase[np] = (uint32_t)r * 128;
        bmask[np] = (uint32_t)((r & 7) << 4);
    }

    float acc[2][4][4];
#pragma unroll
    for (int i = 0; i < 2; i++)
#pragma unroll
        for (int j = 0; j < 4; j++)
#pragma unroll
            for (int r = 0; r < 4; r++) acc[i][j][r] = 0.f;

    auto issue_load = [&](int c, int s) {
        const uint32_t st = smem_base + s * 2 * TILE_BYTES;
        const int ke = c * KCH;
        const uint32_t k0 = (uint32_t)lq * 32;
        const uint32_t d0 = (uint32_t)lrow * 128 + (k0 ^ lmask);
        const uint32_t d1 = (uint32_t)lrow * 128 + ((k0 + 16) ^ lmask);
        const int e0 = ke + (int)(k0 >> 1);
        cp16(st + d0, gAh + e0);
        cp16(st + d1, gAh + e0 + 8);
        cp16(st + TILE_BYTES + d0, gB + e0);
        cp16(st + TILE_BYTES + d1, gB + e0 + 8);
    };

    issue_load(0, 0); CP_COMMIT();
    issue_load(1, 1); CP_COMMIT();

    for (int c = 0; c < NCHUNK; c++) {
        CP_WAIT(1);
        __syncthreads();
        if (c + 2 < NCHUNK) issue_load(c + 2, (c + 2) % 3);
        CP_COMMIT();

        const uint32_t st = smem_base + (c % 3) * 2 * TILE_BYTES;
        const uint32_t stB = st + TILE_BYTES;

#pragma unroll
        for (int ks = 0; ks < 4; ks++) {
            const uint32_t koffA = ks * 32 + a_lkx;
            const uint32_t koffB = ks * 32 + b_lkx;

            uint32_t ah[2][4];
#pragma unroll
            for (int mf = 0; mf < 2; mf++) {
                const uint32_t off = arbase[mf] + (koffA ^ amask[mf]);
                LDSM_X4(ah[mf][0], ah[mf][1], ah[mf][2], ah[mf][3], st + off);
            }
            uint32_t bh[8];
#pragma unroll
            for (int np = 0; np < 2; np++) {
                const uint32_t off = brbase[np] + (koffB ^ bmask[np]);
                LDSM_X4(bh[np * 4 + 0], bh[np * 4 + 1], bh[np * 4 + 2], bh[np * 4 + 3],
                        stB + off);
            }
#pragma unroll
            for (int mf = 0; mf < 2; mf++) {
#pragma unroll
                for (int nf = 0; nf < 4; nf++) {
                    const int ix = (nf >> 1) * 4 + (nf & 1) * 2;
                    mma_f16(acc[mf][nf], ah[mf], bh[ix], bh[ix + 1]);
                }
            }
        }
    }

    const int groupID = lane >> 2;
    const int tig = lane & 3;

    if (LNE == 0) {
        // fp32 epilogue (out-projection)
#pragma unroll
        for (int mf = 0; mf < 2; mf++) {
            const size_t r = (size_t)(m0 + wm + mf * 16 + groupID);
#pragma unroll
            for (int nf = 0; nf < 4; nf++) {
                const int cidx = n0 + wn + nf * 8 + tig * 2;
                *(float2*)(outC + r * GN + cidx) =
                    make_float2(acc[mf][nf][0], acc[mf][nf][1]);
                *(float2*)(outC + (r + 8) * GN + cidx) =
                    make_float2(acc[mf][nf][2], acc[mf][nf][3]);
            }
        }
        return;
    }

    if (blockIdx.z == 2) {
        // V: plain fp16 store
#pragma unroll
        for (int mf = 0; mf < 2; mf++) {
            const size_t r = (size_t)(m0 + wm + mf * 16 + groupID);
#pragma unroll
            for (int nf = 0; nf < 4; nf++) {
                const int cidx = n0 + wn + nf * 8 + tig * 2;
                *(uint32_t*)(outV + r * GN + cidx) =
                    packh2(acc[mf][nf][0], acc[mf][nf][1]);
                *(uint32_t*)(outV + (r + 8) * GN + cidx) =
                    packh2(acc[mf][nf][2], acc[mf][nf][3]);
            }
        }
        return;
    }

    // K (z=0) / Q (z=1): fused per-head LayerNorm epilogue.
    // Cols n0..n0+127 = 2 heads; each head's 64 cols held by 2 n-warp groups.
    {
        const float* lw = (blockIdx.z == 0) ? lwk : lwq;
        const float* lb = (blockIdx.z == 0) ? lbk : lbq;
        __half* Oh = (blockIdx.z == 0) ? outK : outQ;
        const float scale = (blockIdx.z == 0) ? 1.0f : 0.125f;
        float2* part = (float2*)smem;   // [128 rows][4 col-quarters]

        __syncthreads();   // mainloop smem no longer needed
#pragma unroll
        for (int mf = 0; mf < 2; mf++) {
            float s0 = 0.f, ss0 = 0.f, s1 = 0.f, ss1 = 0.f;
#pragma unroll
            for (int nf = 0; nf < 4; nf++) {
                s0 += acc[mf][nf][0] + acc[mf][nf][1];
                ss0 += acc[mf][nf][0] * acc[mf][nf][0]
                     + acc[mf][nf][1] * acc[mf][nf][1];
                s1 += acc[mf][nf][2] + acc[mf][nf][3];
                ss1 += acc[mf][nf][2] * acc[mf][nf][2]
                     + acc[mf][nf][3] * acc[mf][nf][3];
            }
            s0 += __shfl_xor_sync(0xffffffffu, s0, 1);
            s0 += __shfl_xor_sync(0xffffffffu, s0, 2);
            ss0 += __shfl_xor_sync(0xffffffffu, ss0, 1);
            ss0 += __shfl_xor_sync(0xffffffffu, ss0, 2);
            s1 += __shfl_xor_sync(0xffffffffu, s1, 1);
            s1 += __shfl_xor_sync(0xffffffffu, s1, 2);
            ss1 += __shfl_xor_sync(0xffffffffu, ss1, 1);
            ss1 += __shfl_xor_sync(0xffffffffu, ss1, 2);
            if (tig == 0) {
                part[(wm + mf * 16 + groupID) * 4 + (wn >> 5)] =
                    make_float2(s0, ss0);
                part[(wm + mf * 16 + groupID + 8) * 4 + (wn >> 5)] =
                    make_float2(s1, ss1);
            }
        }
        __syncthreads();

        const int wpair = (wn >> 6) * 2;   // head's quarter pair base
        float lww[8], lbb[8];
#pragma unroll
        for (int nf = 0; nf < 4; nf++) {
            const int cl = (wn & 63) + nf * 8 + tig * 2;
            lww[nf * 2 + 0] = lw[cl];     lww[nf * 2 + 1] = lw[cl + 1];
            lbb[nf * 2 + 0] = lb[cl];     lbb[nf * 2 + 1] = lb[cl + 1];
        }
#pragma unroll
        for (int mf = 0; mf < 2; mf++) {
            const int r0 = wm + mf * 16 + groupID;
            float2 pa = part[r0 * 4 + wpair];
            float2 pb = part[r0 * 4 + wpair + 1];
            const float mean0 = (pa.x + pb.x) * (1.f / 64.f);
            const float var0 = (pa.y + pb.y) * (1.f / 64.f) - mean0 * mean0;
            const float rs0 = rsqrtf(var0 + EPS_);
            float2 pc = part[(r0 + 8) * 4 + wpair];
            float2 pd = part[(r0 + 8) * 4 + wpair + 1];
            const float mean1 = (pc.x + pd.x) * (1.f / 64.f);
            const float var1 = (pc.y + pd.y) * (1.f / 64.f) - mean1 * mean1;
            const float rs1 = rsqrtf(var1 + EPS_);
#pragma unroll
            for (int nf = 0; nf < 4; nf++) {
                const int cidx = n0 + wn + nf * 8 + tig * 2;
                float a0 = ((acc[mf][nf][0] - mean0) * rs0 * lww[nf * 2 + 0]
                            + lbb[nf * 2 + 0]) * scale;
                float a1 = ((acc[mf][nf][1] - mean0) * rs0 * lww[nf * 2 + 1]
                            + lbb[nf * 2 + 1]) * scale;
                float a2 = ((acc[mf][nf][2] - mean1) * rs1 * lww[nf * 2 + 0]
                            + lbb[nf * 2 + 0]) * scale;
                float a3 = ((acc[mf][nf][3] - mean1) * rs1 * lww[nf * 2 + 1]
                            + lbb[nf * 2 + 1]) * scale;
                *(uint32_t*)(Oh + (size_t)(m0 + r0) * GN + cidx) = packh2(a0, a1);
                *(uint32_t*)(Oh + (size_t)(m0 + r0 + 8) * GN + cidx) = packh2(a2, a3);
            }
        }
    }
}

// ============================================================================
// Tensor-core causal flash attention, fp16, fixed-shift softmax.
// (unchanged from R14 — validated)
// ============================================================================
#define ATT_SMEM (8192 + 3 * 16384)
#define SM_SHIFT 4.0f

__global__ __launch_bounds__(128, 4) void attn_tc(
    const __half* __restrict__ q2h, const __half* __restrict__ k2h,
    const __half* __restrict__ v2h, __half* __restrict__ ohp) {
    extern __shared__ __align__(1024) char smem[];
    const uint32_t sb = smem_u32(smem);

    const int tid = threadIdx.x;
    const int lane = tid & 31;
    const int wid = tid >> 5;
    const int bh = blockIdx.y;
    const int b = bh >> 4, h = bh & 15;
    const int i0 = (int)(gridDim.x - 1 - blockIdx.x) * 64;
    const int nt = i0 >> 6;
    const size_t hoff = (size_t)b * T_ * E_ + (size_t)h * 64;

    const int row = tid >> 1;
    const int half = tid & 1;
    const uint32_t smask = (uint32_t)((row & 7) << 4);

    const __half* gq = q2h + hoff + (size_t)(i0 + row) * E_ + half * 32;
    const __half* gk = k2h + hoff;
    const __half* gv = v2h + hoff;

    auto issue_tile = [&](int t, int s) {
        const uint32_t st = sb + 8192 + (uint32_t)s * 16384;
        const __half* rk = gk + (size_t)(t * 64 + row) * E_ + half * 32;
        const __half* rv = gv + (size_t)(t * 64 + row) * E_ + half * 32;
#pragma unroll
        for (int v = 0; v < 4; v++) {
            const uint32_t colb = half * 64 + v * 16;
            const uint32_t d = row * 128 + (colb ^ smask);
            cp16(st + d,        rk + v * 8);
            cp16(st + 8192 + d, rv + v * 8);
        }
    };

    {
#pragma unroll
        for (int v = 0; v < 4; v++) {
            const uint32_t colb = half * 64 + v * 16;
            const uint32_t d = row * 128 + (colb ^ smask);
            cp16(sb + d, gq + v * 8);
        }
        issue_tile(0, 0); CP_COMMIT();
        if (nt >= 1) issue_tile(1, 1);
        CP_COMMIT();
    }

    const int gid = lane >> 2, tig = lane & 3;
    const int wm = wid * 16;
    const int a_lrow = wm + (lane & 7) + ((lane >> 3) & 1) * 8;
    const uint32_t a_off = (uint32_t)a_lrow * 128;
    const uint32_t a_lkx = ((lane >> 4) & 1) * 16;
    const uint32_t a_mask = (uint32_t)((a_lrow & 7) << 4);
    const int b_lrow = (lane & 7) + ((lane >> 4) & 1) * 8;
    const uint32_t b_lkx = ((lane >> 3) & 1) * 16;
    const int vt_r = ((lane >> 3) & 1) * 8 + (lane & 7);
    const uint32_t vt_cx = ((lane >> 4) & 1) * 16;
    const int il0 = wm + gid, il1 = wm + gid + 8;

    float oacc[8][4];
#pragma unroll
    for (int i = 0; i < 8; i++)
#pragma unroll
        for (int r = 0; r < 4; r++) oacc[i][r] = 0.f;
    float l0 = 0.f, l1 = 0.f;
    uint32_t aP[16];
    uint32_t aQ[4][4];

    auto do_S_softmax = [&](uint32_t stK, bool isLast) {
#pragma unroll
        for (int jg = 0; jg < 4; jg++) {
            float s8[8];
#pragma unroll
            for (int r = 0; r < 8; r++) s8[r] = 0.f;
            const int r2 = jg * 16 + b_lrow;
            const uint32_t rbase = (uint32_t)r2 * 128;
            const uint32_t rmask = (uint32_t)((r2 & 7) << 4);
#pragma unroll
            for (int kc = 0; kc < 4; kc++) {
                uint32_t kb[4];
                LDSM_X4(kb[0], kb[1], kb[2], kb[3],
                        stK + rbase + (((uint32_t)kc * 32 + b_lkx) ^ rmask));
                mma_f16(&s8[0], aQ[kc], kb[0], kb[1]);
                mma_f16(&s8[4], aQ[kc], kb[2], kb[3]);
            }
            if (isLast) {
                const int jc0 = jg * 16 + tig * 2;
                const int jc1 = jc0 + 8;
                if (jc0 > il0)     s8[0] = -1e30f;
                if (jc0 + 1 > il0) s8[1] = -1e30f;
                if (jc0 > il1)     s8[2] = -1e30f;
                if (jc0 + 1 > il1) s8[3] = -1e30f;
                if (jc1 > il0)     s8[4] = -1e30f;
                if (jc1 + 1 > il0) s8[5] = -1e30f;
                if (jc1 > il1)     s8[6] = -1e30f;
                if (jc1 + 1 > il1) s8[7] = -1e30f;
            }
#pragma unroll
            for (int r = 0; r < 8; r++) s8[r] = __expf(s8[r] - SM_SHIFT);
            l0 += s8[0] + s8[1] + s8[4] + s8[5];
            l1 += s8[2] + s8[3] + s8[6] + s8[7];
            aP[jg * 4 + 0] = packh2(s8[0], s8[1]);
            aP[jg * 4 + 1] = packh2(s8[2], s8[3]);
            aP[jg * 4 + 2] = packh2(s8[4], s8[5]);
            aP[jg * 4 + 3] = packh2(s8[6], s8[7]);
        }
    };

    auto do_PV = [&](uint32_t stV) {
#pragma unroll
        for (int kc = 0; kc < 4; kc++) {
            const int jr = kc * 16 + vt_r;
            const uint32_t vrow = (uint32_t)jr * 128;
            const uint32_t vmask = (uint32_t)((jr & 7) << 4);
#pragma unroll
            for (int dp = 0; dp < 4; dp++) {
                const uint32_t off = vrow + (((uint32_t)dp * 32 + vt_cx) ^ vmask);
                uint32_t vv[4];
                LDSM_X4_T(vv[0], vv[1], vv[2], vv[3], stV + off);
                mma_f16(oacc[dp * 2], &aP[kc * 4], vv[0], vv[1]);
                mma_f16(oacc[dp * 2 + 1], &aP[kc * 4], vv[2], vv[3]);
            }
        }
    };

    for (int jt = 0; jt <= nt; jt++) {
        CP_WAIT(1);
        __syncthreads();
        if (jt == 0) {
#pragma unroll
            for (int kc = 0; kc < 4; kc++)
                LDSM_X4(aQ[kc][0], aQ[kc][1], aQ[kc][2], aQ[kc][3],
                        sb + a_off + (((uint32_t)kc * 32 + a_lkx) ^ a_mask));
        }
        if (jt + 2 <= nt) issue_tile(jt + 2, (jt + 2) % 3);
        CP_COMMIT();

        const uint32_t st = sb + 8192 + (uint32_t)(jt % 3) * 16384;
        do_S_softmax(st, jt == nt);
        do_PV(st + 8192);
    }

    l0 += __shfl_xor_sync(0xffffffffu, l0, 1);
    l0 += __shfl_xor_sync(0xffffffffu, l0, 2);
    l1 += __shfl_xor_sync(0xffffffffu, l1, 1);
    l1 += __shfl_xor_sync(0xffffffffu, l1, 2);

    const float inv0 = 1.f / l0, inv1 = 1.f / l1;
    const int r0g = b * T_ + i0 + wm + gid;
#pragma unroll
    for (int df = 0; df < 8; df++) {
        const int d = df * 8 + tig * 2;
        const size_t i1 = (size_t)r0g * E_ + h * 64 + d;
        const size_t i2 = (size_t)(r0g + 8) * E_ + h * 64 + d;
        *(uint32_t*)(ohp + i1) = packh2(oacc[df][0] * inv0, oacc[df][1] * inv0);
        *(uint32_t*)(ohp + i2) = packh2(oacc[df][2] * inv1, oacc[df][3] * inv1);
    }
}

// ---------------------------------------------------------------------------
// Launch
// ---------------------------------------------------------------------------
extern "C" void kernel_launch(void* const* d_in, const int* in_sizes, int n_in,
                              void* d_out, int out_size) {
    const float* x     = (const float*)d_in[0];
    const float* Wk    = (const float*)d_in[1];
    const float* Wq    = (const float*)d_in[2];
    const float* Wv    = (const float*)d_in[3];
    const float* Wu    = (const float*)d_in[4];
    const float* kln_w = (const float*)d_in[5];
    const float* kln_b = (const float*)d_in[6];
    const float* qln_w = (const float*)d_in[7];
    const float* qln_b = (const float*)d_in[8];
    float* out = (float*)d_out;

    __half *xh, *oh, *w16, *q2h, *k2h, *v2h;
    cudaGetSymbolAddress((void**)&xh, g_xh);
    cudaGetSymbolAddress((void**)&oh, g_oh);
    cudaGetSymbolAddress((void**)&w16, g_w16);
    cudaGetSymbolAddress((void**)&q2h, g_q2h);
    cudaGetSymbolAddress((void**)&k2h, g_k2h);
    cudaGetSymbolAddress((void**)&v2h, g_v2h);

    __half* wk16 = w16 + 0 * (size_t)E_ * E_;
    __half* wq16 = w16 + 1 * (size_t)E_ * E_;
    __half* wv16 = w16 + 2 * (size_t)E_ * E_;
    __half* wu16 = w16 + 3 * (size_t)E_ * E_;

    cudaFuncSetAttribute(gemm_f16<1>,
                         cudaFuncAttributeMaxDynamicSharedMemorySize, SMEM_G);
    cudaFuncSetAttribute(gemm_f16<0>,
                         cudaFuncAttributeMaxDynamicSharedMemorySize, SMEM_G);
    cudaFuncSetAttribute(attn_tc,
                         cudaFuncAttributeMaxDynamicSharedMemorySize, ATT_SMEM);

    const int nconv = ROWS_ * E_ / 4 + 4 * (E_ * E_ / 4);
    conv_all_f16<<<(nconv + 255) / 256, 256>>>(x, Wk, Wq, Wv, Wu, xh, w16);

    // QKV with fused K/Q LayerNorm epilogue (z0=K, z1=Q, z2=V)
    dim3 gQKV(E_ / 128, ROWS_ / 128, 3);
    gemm_f16<1><<<gQKV, 512, SMEM_G>>>(
        xh, wk16, wq16, wv16, k2h, q2h, v2h, nullptr,
        kln_w, kln_b, qln_w, qln_b);

    dim3 gAttn(T_ / 64, B_ * H_);
    attn_tc<<<gAttn, 128, ATT_SMEM>>>(q2h, k2h, v2h, oh);

    // out-projection: fp32 output
    dim3 gOut(E_ / 128, ROWS_ / 128, 1);
    gemm_f16<0><<<gOut, 512, SMEM_G>>>(
        oh, wu16, wu16, wu16, nullptr, nullptr, nullptr, out,
        nullptr, nullptr, nullptr, nullptr);
}